// round 1
// baseline (speedup 1.0000x reference)
#include <cuda_runtime.h>
#include <cuda_bf16.h>
#include <cstdint>

// Syndrome length is fixed at 256 bits for this problem family.
#define SL 256
#define MAX_T 4096   // scratch sized generously; problem uses T=2048

// Scratch: packed table keys (4 x u64 per row) + 64-bit fold hash per row.
// __device__ globals per harness rules (no cudaMalloc allowed).
__device__ uint64_t g_pk[MAX_T * 4];
__device__ uint64_t g_hash[MAX_T];

// ---------------------------------------------------------------------------
// Kernel 1: pack table keys into 256-bit integers + fold hash.
// One warp per table row; 8 ballots turn 256 floats into 8 u32 words.
// ---------------------------------------------------------------------------
__global__ void pack_table_kernel(const float* __restrict__ tk, int T) {
    int warp = (blockIdx.x * blockDim.x + threadIdx.x) >> 5;
    int lane = threadIdx.x & 31;
    if (warp >= T) return;

    const float* row = tk + (size_t)warp * SL;
    uint32_t w[8];
#pragma unroll
    for (int i = 0; i < 8; i++) {
        float v = row[i * 32 + lane];            // coalesced
        w[i] = __ballot_sync(0xffffffffu, v > 0.5f);  // warp-uniform result
    }
    uint64_t k0 = (uint64_t)w[0] | ((uint64_t)w[1] << 32);
    uint64_t k1 = (uint64_t)w[2] | ((uint64_t)w[3] << 32);
    uint64_t k2 = (uint64_t)w[4] | ((uint64_t)w[5] << 32);
    uint64_t k3 = (uint64_t)w[6] | ((uint64_t)w[7] << 32);

    if (lane == 0) {
        uint64_t* pk = &g_pk[(size_t)warp * 4];
        pk[0] = k0; pk[1] = k1; pk[2] = k2; pk[3] = k3;
        g_hash[warp] = k0
                     ^ (k1 * 0x9E3779B97F4A7C15ull)
                     ^ (k2 * 0xC2B2AE3D27D4EB4Full)
                     ^ (k3 * 0x165667B19E3779F9ull);
    }
}

// ---------------------------------------------------------------------------
// Kernel 2: one warp per query. Pack query via ballots, scan smem hash table,
// verify rare hash-hits against full packed key, copy value row or zeros.
// ---------------------------------------------------------------------------
__global__ __launch_bounds__(256) void lookup_kernel(
    const float* __restrict__ syn,
    const float* __restrict__ tv,
    float* __restrict__ out,
    int B, int T)
{
    __shared__ uint64_t sh_hash[MAX_T];

    // Cooperative load of all T hashes into shared (coalesced u64 loads).
    for (int i = threadIdx.x; i < T; i += blockDim.x)
        sh_hash[i] = g_hash[i];
    __syncthreads();

    int lane = threadIdx.x & 31;
    int q = blockIdx.x * (blockDim.x >> 5) + (threadIdx.x >> 5);
    if (q >= B) return;

    // Pack this query's 256 floats into 4 u64 (every lane holds the full key:
    // ballot results are warp-uniform).
    const float* row = syn + (size_t)q * SL;
    uint32_t w[8];
#pragma unroll
    for (int i = 0; i < 8; i++) {
        float v = row[i * 32 + lane];            // coalesced
        w[i] = __ballot_sync(0xffffffffu, v > 0.5f);
    }
    uint64_t q0 = (uint64_t)w[0] | ((uint64_t)w[1] << 32);
    uint64_t q1 = (uint64_t)w[2] | ((uint64_t)w[3] << 32);
    uint64_t q2 = (uint64_t)w[4] | ((uint64_t)w[5] << 32);
    uint64_t q3 = (uint64_t)w[6] | ((uint64_t)w[7] << 32);
    uint64_t qh = q0
                ^ (q1 * 0x9E3779B97F4A7C15ull)
                ^ (q2 * 0xC2B2AE3D27D4EB4Full)
                ^ (q3 * 0x165667B19E3779F9ull);

    // Scan: lane l checks entries l, l+32, l+64, ... Hash filter first; the
    // full 256-bit verify guarantees correctness regardless of collisions.
    int best = 0x7fffffff;
    for (int i = lane; i < T; i += 32) {
        if (sh_hash[i] == qh) {
            const uint64_t* pk = &g_pk[(size_t)i * 4];
            if (pk[0] == q0 && pk[1] == q1 && pk[2] == q2 && pk[3] == q3)
                best = min(best, i);   // keep FIRST match (reference argmax)
        }
    }
    // Warp min-reduction.
#pragma unroll
    for (int off = 16; off; off >>= 1)
        best = min(best, __shfl_xor_sync(0xffffffffu, best, off));

    // Emit: hit -> memorized flip vector; miss -> zeros. Coalesced stores.
    float* orow = out + (size_t)q * SL;
    if (best < T) {
        const float* vrow = tv + (size_t)best * SL;
#pragma unroll
        for (int i = 0; i < 8; i++)
            orow[i * 32 + lane] = vrow[i * 32 + lane];
    } else {
#pragma unroll
        for (int i = 0; i < 8; i++)
            orow[i * 32 + lane] = 0.0f;
    }
}

// ---------------------------------------------------------------------------
// Launch: pack table, then lookup. Both graph-capturable, allocation-free.
// ---------------------------------------------------------------------------
extern "C" void kernel_launch(void* const* d_in, const int* in_sizes, int n_in,
                              void* d_out, int out_size) {
    const float* syn = (const float*)d_in[0];   // [B, 256]
    const float* tk  = (const float*)d_in[1];   // [T, 256]
    const float* tv  = (const float*)d_in[2];   // [T, 256]
    float* out = (float*)d_out;                 // [B, 256]

    int B = in_sizes[0] / SL;
    int T = in_sizes[1] / SL;

    // Kernel 1: one warp per table row, 256 threads/block = 8 rows/block.
    int pack_blocks = (T + 7) / 8;
    pack_table_kernel<<<pack_blocks, 256>>>(tk, T);

    // Kernel 2: one warp per query, 256 threads/block = 8 queries/block.
    int lk_blocks = (B + 7) / 8;
    lookup_kernel<<<lk_blocks, 256>>>(syn, tv, out, B, T);
}

// round 2
// speedup vs baseline: 1.1255x; 1.1255x over previous
#include <cuda_runtime.h>
#include <cuda_bf16.h>
#include <cstdint>

#define SL 256        // syndrome bit length (fixed for this problem family)
#define MAX_T 4096    // scratch capacity for table entries (problem uses 2048)
#define NB 8192       // hash-table slots (power of 2, load factor <= 0.5)

// Scratch in __device__ globals (no allocation allowed).
// g_table: 0 = empty, else entry_index + 1. Zero-init == all-empty.
// Insertion is idempotent across graph replays (slot already holding our tag
// counts as success), so no clearing pass is needed.
__device__ uint64_t     g_pk[MAX_T * 4];
__device__ unsigned int g_table[NB];

__device__ __forceinline__ uint64_t mix64(uint64_t x) {
    // splitmix64 finalizer
    x ^= x >> 30; x *= 0xBF58476D1CE4E5B9ull;
    x ^= x >> 27; x *= 0x94D049BB133111EBull;
    x ^= x >> 31;
    return x;
}

__device__ __forceinline__ uint64_t fold_hash(uint64_t k0, uint64_t k1,
                                              uint64_t k2, uint64_t k3) {
    return k0 ^ (k1 * 0x9E3779B97F4A7C15ull)
              ^ (k2 * 0xC2B2AE3D27D4EB4Full)
              ^ (k3 * 0x165667B19E3779F9ull);
}

// ---------------------------------------------------------------------------
// Kernel 1: pack table keys into 256-bit integers and insert into the
// open-addressed hash table. One warp per table row.
// ---------------------------------------------------------------------------
__global__ void build_table_kernel(const float* __restrict__ tk, int T) {
    int row_i = (blockIdx.x * blockDim.x + threadIdx.x) >> 5;
    int lane  = threadIdx.x & 31;
    if (row_i >= T) return;

    const float* row = tk + (size_t)row_i * SL;
    uint32_t w[8];
#pragma unroll
    for (int i = 0; i < 8; i++) {
        float v = row[i * 32 + lane];                   // coalesced 128B
        w[i] = __ballot_sync(0xffffffffu, v > 0.5f);    // warp-uniform
    }
    uint64_t k0 = (uint64_t)w[0] | ((uint64_t)w[1] << 32);
    uint64_t k1 = (uint64_t)w[2] | ((uint64_t)w[3] << 32);
    uint64_t k2 = (uint64_t)w[4] | ((uint64_t)w[5] << 32);
    uint64_t k3 = (uint64_t)w[6] | ((uint64_t)w[7] << 32);

    if (lane == 0) {
        uint64_t* pk = &g_pk[(size_t)row_i * 4];
        pk[0] = k0; pk[1] = k1; pk[2] = k2; pk[3] = k3;

        uint64_t h = fold_hash(k0, k1, k2, k3);
        unsigned b = (unsigned)mix64(h) & (NB - 1);
        unsigned tag = (unsigned)row_i + 1u;
        // Linear probe insert; idempotent on replay (prev == tag -> done).
        for (;;) {
            unsigned prev = atomicCAS(&g_table[b], 0u, tag);
            if (prev == 0u || prev == tag) break;
            b = (b + 1) & (NB - 1);
        }
    }
}

// ---------------------------------------------------------------------------
// Kernel 2: one warp per query. Pack via ballots, O(1) hash probe on lane 0
// (full 256-bit verify, min-index over the probe cluster preserves the
// reference's first-match semantics), then float4 copy of value row / zeros.
// ---------------------------------------------------------------------------
__global__ __launch_bounds__(256) void lookup_kernel(
    const float* __restrict__ syn,
    const float* __restrict__ tv,
    float* __restrict__ out,
    int B)
{
    int lane = threadIdx.x & 31;
    int q = blockIdx.x * (blockDim.x >> 5) + (threadIdx.x >> 5);
    if (q >= B) return;

    // Pack the query; ballot results are warp-uniform so every lane holds the key.
    const float* row = syn + (size_t)q * SL;
    uint32_t w[8];
#pragma unroll
    for (int i = 0; i < 8; i++) {
        float v = row[i * 32 + lane];                   // coalesced 128B
        w[i] = __ballot_sync(0xffffffffu, v > 0.5f);
    }
    uint64_t q0 = (uint64_t)w[0] | ((uint64_t)w[1] << 32);
    uint64_t q1 = (uint64_t)w[2] | ((uint64_t)w[3] << 32);
    uint64_t q2 = (uint64_t)w[4] | ((uint64_t)w[5] << 32);
    uint64_t q3 = (uint64_t)w[6] | ((uint64_t)w[7] << 32);

    int best = 0x7fffffff;
    if (lane == 0) {
        uint64_t h = fold_hash(q0, q1, q2, q3);
        unsigned b = (unsigned)mix64(h) & (NB - 1);
        // Probe the whole cluster (until an empty slot) so duplicate keys
        // still resolve to the minimum table index.
        for (;;) {
            unsigned v = g_table[b];                    // L2-resident, 32KB
            if (v == 0u) break;
            int idx = (int)v - 1;
            const uint64_t* pk = &g_pk[(size_t)idx * 4];
            if (pk[0] == q0 && pk[1] == q1 && pk[2] == q2 && pk[3] == q3)
                best = min(best, idx);
            b = (b + 1) & (NB - 1);
        }
    }
    best = __shfl_sync(0xffffffffu, best, 0);

    // Vectorized emit: 256 floats = 64 float4; 2 per lane.
    float4* orow4 = (float4*)(out + (size_t)q * SL);
    if (best != 0x7fffffff) {
        const float4* vrow4 = (const float4*)(tv + (size_t)best * SL);
        float4 a = vrow4[lane];
        float4 c = vrow4[lane + 32];
        orow4[lane]      = a;
        orow4[lane + 32] = c;
    } else {
        float4 z = make_float4(0.f, 0.f, 0.f, 0.f);
        orow4[lane]      = z;
        orow4[lane + 32] = z;
    }
}

// ---------------------------------------------------------------------------
extern "C" void kernel_launch(void* const* d_in, const int* in_sizes, int n_in,
                              void* d_out, int out_size) {
    const float* syn = (const float*)d_in[0];   // [B, 256]
    const float* tk  = (const float*)d_in[1];   // [T, 256]
    const float* tv  = (const float*)d_in[2];   // [T, 256]
    float* out = (float*)d_out;                 // [B, 256]

    int B = in_sizes[0] / SL;
    int T = in_sizes[1] / SL;

    build_table_kernel<<<(T + 7) / 8, 256>>>(tk, T);
    lookup_kernel<<<(B + 7) / 8, 256>>>(syn, tv, out, B);
}

// round 6
// speedup vs baseline: 1.3068x; 1.1611x over previous
#include <cuda_runtime.h>
#include <cuda_bf16.h>
#include <cstdint>

#define SL 256        // syndrome bit length (fixed for this problem family)
#define MAX_T 4096    // scratch capacity for table entries (problem uses 2048)
#define NB 8192       // hash-table slots (power of 2, load factor <= 0.5)

// Scratch in __device__ globals (no allocation allowed).
// g_table: 0 = empty, else entry_index + 1. Zero-init == all-empty.
// Insertion is idempotent across graph replays.
__device__ uint64_t     g_pk[MAX_T * 4];
__device__ unsigned int g_table[NB];

__device__ __forceinline__ uint64_t mix64(uint64_t x) {
    x ^= x >> 30; x *= 0xBF58476D1CE4E5B9ull;
    x ^= x >> 27; x *= 0x94D049BB133111EBull;
    x ^= x >> 31;
    return x;
}

__device__ __forceinline__ uint64_t fold_hash(uint64_t k0, uint64_t k1,
                                              uint64_t k2, uint64_t k3) {
    return k0 ^ (k1 * 0x9E3779B97F4A7C15ull)
              ^ (k2 * 0xC2B2AE3D27D4EB4Full)
              ^ (k3 * 0x165667B19E3779F9ull);
}

// ---------------------------------------------------------------------------
// Kernel 1: pack table keys -> 256-bit ints, insert idx+1 into hash table.
// One warp per row. 512-thread blocks for more resident warps.
// ---------------------------------------------------------------------------
__global__ __launch_bounds__(512) void build_table_kernel(
    const float* __restrict__ tk, int T)
{
    int row_i = (blockIdx.x * blockDim.x + threadIdx.x) >> 5;
    int lane  = threadIdx.x & 31;
    if (row_i >= T) return;

    const float* row = tk + (size_t)row_i * SL;
    uint32_t w[8];
#pragma unroll
    for (int i = 0; i < 8; i++) {
        float v = row[i * 32 + lane];                   // coalesced 128B
        w[i] = __ballot_sync(0xffffffffu, v > 0.5f);    // warp-uniform
    }
    uint64_t k0 = (uint64_t)w[0] | ((uint64_t)w[1] << 32);
    uint64_t k1 = (uint64_t)w[2] | ((uint64_t)w[3] << 32);
    uint64_t k2 = (uint64_t)w[4] | ((uint64_t)w[5] << 32);
    uint64_t k3 = (uint64_t)w[6] | ((uint64_t)w[7] << 32);

    // Vectorized pk store from two lanes (32B total).
    if (lane == 0)
        *(ulonglong2*)&g_pk[(size_t)row_i * 4]     = make_ulonglong2(k0, k1);
    if (lane == 1)
        *(ulonglong2*)&g_pk[(size_t)row_i * 4 + 2] = make_ulonglong2(k2, k3);

    if (lane == 0) {
        uint64_t h = fold_hash(k0, k1, k2, k3);
        unsigned b = (unsigned)mix64(h) & (NB - 1);
        unsigned tag = (unsigned)row_i + 1u;
        for (;;) {
            unsigned prev = atomicCAS(&g_table[b], 0u, tag);
            if (prev == 0u || prev == tag) break;       // idempotent on replay
            b = (b + 1) & (NB - 1);
        }
    }
}

// ---------------------------------------------------------------------------
// Kernel 2: one warp per query. Warp-parallel probe: all 32 lanes read one
// coalesced 128B window of the table; ballot finds the cluster end; each
// candidate lane verifies its own 32B packed key in parallel; min-reduce
// preserves first-match semantics. Then float4 copy of value row / zeros.
// ---------------------------------------------------------------------------
__global__ __launch_bounds__(256) void lookup_kernel(
    const float* __restrict__ syn,
    const float* __restrict__ tv,
    float* __restrict__ out,
    int B)
{
    int lane = threadIdx.x & 31;
    int q = blockIdx.x * (blockDim.x >> 5) + (threadIdx.x >> 5);
    if (q >= B) return;

    // Pack query via ballots (results warp-uniform: every lane holds the key).
    const float* row = syn + (size_t)q * SL;
    uint32_t w[8];
#pragma unroll
    for (int i = 0; i < 8; i++) {
        float v = row[i * 32 + lane];                   // coalesced 128B
        w[i] = __ballot_sync(0xffffffffu, v > 0.5f);
    }
    uint64_t q0 = (uint64_t)w[0] | ((uint64_t)w[1] << 32);
    uint64_t q1 = (uint64_t)w[2] | ((uint64_t)w[3] << 32);
    uint64_t q2 = (uint64_t)w[4] | ((uint64_t)w[5] << 32);
    uint64_t q3 = (uint64_t)w[6] | ((uint64_t)w[7] << 32);

    uint64_t h = fold_hash(q0, q1, q2, q3);
    unsigned b0 = (unsigned)mix64(h) & (NB - 1);

    int best = 0x7fffffff;
    for (;;) {
        // One coalesced 128B read covers 32 slots of the cluster.
        unsigned slot = (b0 + lane) & (NB - 1);
        unsigned v = g_table[slot];

        unsigned empty_mask = __ballot_sync(0xffffffffu, v == 0u);
        int first_empty = empty_mask ? (__ffs(empty_mask) - 1) : 32;

        // Lanes inside the cluster verify their candidate in parallel.
        if (v != 0u && lane < first_empty) {
            int idx = (int)v - 1;
            const uint64_t* pk = &g_pk[(size_t)idx * 4];
            ulonglong2 a = *(const ulonglong2*)pk;       // 16B
            ulonglong2 c = *(const ulonglong2*)(pk + 2); // 16B
            if (a.x == q0 && a.y == q1 && c.x == q2 && c.y == q3)
                best = min(best, idx);                   // first match = min idx
        }
        if (first_empty < 32) break;                     // cluster ends here
        b0 = (b0 + 32) & (NB - 1);                       // essentially never
    }
    // Warp min-reduction.
#pragma unroll
    for (int off = 16; off; off >>= 1)
        best = min(best, __shfl_xor_sync(0xffffffffu, best, off));

    // Vectorized emit: 256 floats = 64 float4; 2 per lane.
    float4* orow4 = (float4*)(out + (size_t)q * SL);
    if (best != 0x7fffffff) {
        const float4* vrow4 = (const float4*)(tv + (size_t)best * SL);
        float4 a = vrow4[lane];
        float4 c = vrow4[lane + 32];
        orow4[lane]      = a;
        orow4[lane + 32] = c;
    } else {
        float4 z = make_float4(0.f, 0.f, 0.f, 0.f);
        orow4[lane]      = z;
        orow4[lane + 32] = z;
    }
}

// ---------------------------------------------------------------------------
extern "C" void kernel_launch(void* const* d_in, const int* in_sizes, int n_in,
                              void* d_out, int out_size) {
    const float* syn = (const float*)d_in[0];   // [B, 256]
    const float* tk  = (const float*)d_in[1];   // [T, 256]
    const float* tv  = (const float*)d_in[2];   // [T, 256]
    float* out = (float*)d_out;                 // [B, 256]

    int B = in_sizes[0] / SL;
    int T = in_sizes[1] / SL;

    build_table_kernel<<<(T + 15) / 16, 512>>>(tk, T);
    lookup_kernel<<<(B + 7) / 8, 256>>>(syn, tv, out, B);
}